// round 13
// baseline (speedup 1.0000x reference)
#include <cuda_runtime.h>
#include <cuda_fp16.h>
#include <cstdint>

#define IND       1024
#define ODIM      128
#define BATCHN    65536
#define BM        64
#define KC        32                  // k-elems per chunk
#define NITER     (IND / KC)          // 32
#define NTHR      256
#define NS        3

#define PITCHB    80                  // bytes per fp16 smem row (20r mod 32 distinct)
#define PITCHH    40
#define PANEL_H   (ODIM * PITCHH)     // 5120 halves per W k-panel (10240 B)
#define W_BYTES   10240

#define SM_MBAR     0                 // 6 mbarriers: [gemm][slot]
#define SM_COEF     256
#define SM_SLOT     2048
#define SLOT_BYTES  30720             // x 5120 + y 5120 + W0 10240 + W1 10240
#define TO_X        0
#define TO_Y        5120
#define TO_W0       10240
#define TO_W1       20480
#define SMEM_TOTAL  (SM_SLOT + NS * SLOT_BYTES)     // 94208 -> 2 CTAs/SM
#define EXP         132

typedef uint32_t U32;

__device__ __align__(1024) __half g_W0h[NITER * PANEL_H];
__device__ __align__(1024) __half g_W1h[NITER * PANEL_H];

// ---------------- PTX helpers ----------------

static __device__ __forceinline__ U32 s2u(const void* p) {
    U32 a;
    asm("{ .reg .u64 t; cvta.to.shared.u64 t, %1; cvt.u32.u64 %0, t; }" : "=r"(a) : "l"(p));
    return a;
}

static __device__ __forceinline__ void bulk_g2s(U32 dst, const void* src, U32 bytes, U32 mbar) {
    asm volatile("cp.async.bulk.shared::cluster.global.mbarrier::complete_tx::bytes "
                 "[%0], [%1], %2, [%3];"
                 :: "r"(dst), "l"(src), "r"(bytes), "r"(mbar) : "memory");
}

static __device__ __forceinline__ void mbar_init(U32 a, U32 cnt) {
    asm volatile("mbarrier.init.shared.b64 [%0], %1;" :: "r"(a), "r"(cnt) : "memory");
}
static __device__ __forceinline__ void mbar_expect(U32 a, U32 tx) {
    asm volatile("mbarrier.arrive.expect_tx.shared.b64 _, [%0], %1;" :: "r"(a), "r"(tx) : "memory");
}

#define MBAR_WAIT(addr, par) do {                                              \
    asm volatile("{\n\t.reg .pred P1;\n\t"                                     \
        "LAB_W_%=:\n\t"                                                        \
        "mbarrier.try_wait.parity.acquire.cta.shared::cta.b64 P1, [%0], %1, 0x989680;\n\t" \
        "@P1 bra.uni LAB_D_%=;\n\t"                                            \
        "bra.uni LAB_W_%=;\n\t"                                                \
        "LAB_D_%=:\n\t}"                                                       \
        :: "r"(addr), "r"(par) : "memory");                                    \
} while (0)

#define BAR_HALF(id) asm volatile("bar.sync %0, 128;" :: "r"(id) : "memory")

static __device__ __forceinline__ void ldsm4(U32& r0, U32& r1, U32& r2, U32& r3, U32 addr) {
    asm volatile("ldmatrix.sync.aligned.m8n8.x4.shared.b16 {%0,%1,%2,%3}, [%4];"
                 : "=r"(r0), "=r"(r1), "=r"(r2), "=r"(r3) : "r"(addr));
}

static __device__ __forceinline__ void mma16(float* c, U32 a0, U32 a1, U32 a2, U32 a3,
                                             U32 b0, U32 b1) {
    asm volatile("mma.sync.aligned.m16n8k16.row.col.f32.f16.f16.f32 "
                 "{%0,%1,%2,%3}, {%4,%5,%6,%7}, {%8,%9}, {%0,%1,%2,%3};"
                 : "+f"(c[0]), "+f"(c[1]), "+f"(c[2]), "+f"(c[3])
                 : "r"(a0), "r"(a1), "r"(a2), "r"(a3), "r"(b0), "r"(b1));
}

static __device__ __forceinline__ U32 cvt2h(float lo, float hi) {
    U32 r;
    asm("cvt.rn.f16x2.f32 %0, %1, %2;" : "=r"(r) : "f"(hi), "f"(lo));
    return r;
}

// ---------------- weight normalization + fp16 k-panel packing ----------------
__global__ void normalize_kernel(const float* __restrict__ w) {
    int row  = blockIdx.x & (ODIM - 1);
    int half = blockIdx.x >> 7;
    const float* src = w + (size_t)row * (2 * IND) + (size_t)half * IND;
    __half* dst = half ? g_W1h : g_W0h;
    int t = threadIdx.x;  // 256 threads
    float v[4], s = 0.f, s2 = 0.f;
#pragma unroll
    for (int i = 0; i < 4; ++i) { v[i] = src[t + 256 * i]; s += v[i]; s2 += v[i] * v[i]; }
#pragma unroll
    for (int o = 16; o; o >>= 1) {
        s  += __shfl_xor_sync(~0u, s,  o);
        s2 += __shfl_xor_sync(~0u, s2, o);
    }
    __shared__ float sh[18];
    if ((t & 31) == 0) { sh[t >> 5] = s; sh[8 + (t >> 5)] = s2; }
    __syncthreads();
    if (t == 0) {
        float S = 0.f, S2 = 0.f;
#pragma unroll
        for (int i = 0; i < 8; ++i) { S += sh[i]; S2 += sh[8 + i]; }
        float mu = S * (1.f / IND);
        float ss = S2 - (float)IND * mu * mu;
        sh[16] = mu; sh[17] = rsqrtf(ss);
    }
    __syncthreads();
    float mu = sh[16], inv = sh[17];
#pragma unroll
    for (int i = 0; i < 4; ++i) {
        int k  = t + 256 * i;
        int kc = k >> 5, col = k & 31;
        dst[(size_t)kc * PANEL_H + row * PITCHH + col] = __float2half((v[i] - mu) * inv);
    }
    {
        int kc = t >> 3, pc = 32 + (t & 7);
        dst[(size_t)kc * PANEL_H + row * PITCHH + pc] = __float2half(0.f);
    }
}

// ------------- main fused GEMM (split-half pipelines, 3 slots, 2 CTAs/SM) ----------
// Warps 0-3: GEMM0 {x, W0}, named bar 2. Warps 4-7: GEMM1 {y, W1}, named bar 3.
// Each half loads/converts its own activation; its W comes via its own TMA+mbar.

__global__ void __launch_bounds__(NTHR, 2)
gemm_kernel(const float* __restrict__ x, const float* __restrict__ y,
            const float* __restrict__ fc_bias, const float* __restrict__ a0,
            const float* __restrict__ a1, float* __restrict__ out) {
    extern __shared__ char smem[];
    const U32 sb = s2u(smem);
    const int tid = threadIdx.x;
    const int wid = tid >> 5, lid = tid & 31;
    const int m0 = blockIdx.x * BM;

    if (tid == 0) {
#pragma unroll
        for (int k = 0; k < 2 * NS; ++k) mbar_init(sb + SM_MBAR + k * 8, 1);
    }
    if (tid < 128) {
        float* sc = (float*)(smem + SM_COEF);
        sc[tid] = a0[tid]; sc[128 + tid] = a1[tid]; sc[256 + tid] = fc_bias[tid];
    }
    __syncthreads();

    const int g1   = wid >> 2;            // 0: GEMM0, 1: GEMM1
    const int htid = tid & 127;
    const U32 mbb  = sb + SM_MBAR + (U32)(g1 * NS * 8);   // this half's 3 mbars

    // activation load lanes: 128 threads cover 64 rows x 8 chunks; 4 rows/thread
    const int ch = htid & 7;
    const int r0 = htid >> 3;             // 0..15
    const float* act = g1 ? y : x;
    const float* pa  = act + (size_t)(m0 + r0) * IND + ch * 4;
    const size_t rstep = (size_t)16 * IND;
    const U32 toA = g1 ? TO_Y : TO_X;
    const U32 toW = g1 ? TO_W1 : TO_W0;
    const __half* gw = g1 ? g_W1h : g_W0h;
    U32 dA[4];
#pragma unroll
    for (int j = 0; j < 4; ++j)
        dA[j] = toA + (U32)((r0 + 16 * j) * PITCHB + ch * 8);

    // stash 4 float4 (one chunk's worth for this thread) into slot st
    auto stash = [&](U32 st, const float4* v) {
#pragma unroll
        for (int j = 0; j < 4; ++j) {
            U32 h0 = cvt2h(v[j].x, v[j].y), h1 = cvt2h(v[j].z, v[j].w);
            asm volatile("st.shared.v2.b32 [%0], {%1,%2};" :: "r"(st + dA[j]), "r"(h0), "r"(h1));
        }
    };

    // prologue: chunks 0..2 into slots 0..2
#pragma unroll
    for (int s = 0; s < NS; ++s) {
        const U32 st = sb + SM_SLOT + (U32)(s * SLOT_BYTES);
        if (htid == 0) {
            mbar_expect(mbb + s * 8, W_BYTES);
            bulk_g2s(st + toW, gw + (size_t)s * PANEL_H, W_BYTES, mbb + s * 8);
        }
        float4 v[4];
#pragma unroll
        for (int j = 0; j < 4; ++j) v[j] = *(const float4*)(pa + s * KC + j * rstep);
        stash(st, v);
    }

    // warp tiling within the half
    const int wl = wid & 3;
    const int mw = wl & 1;                // m-half (32 rows)
    const int nw = wl >> 1;               // n-half (64 cols)

    const int sel  = lid >> 3;
    const int lrow = lid & 7;
    const int aRowL = (sel & 1) * 8 + lrow;
    const U32 aKb   = (U32)((sel >> 1) * 16);
    const int bRowL = sel * 8 + lrow;

    U32 aOff[2];
#pragma unroll
    for (int mt = 0; mt < 2; ++mt)
        aOff[mt] = toA + (U32)((mw * 32 + mt * 16 + aRowL) * PITCHB) + aKb;
    U32 bOff[2];
#pragma unroll
    for (int g = 0; g < 2; ++g)
        bOff[g] = toW + (U32)((nw * 64 + g * 32 + bRowL) * PITCHB);

    float acc[2][8][4];
#pragma unroll
    for (int mt = 0; mt < 2; ++mt)
#pragma unroll
        for (int nt = 0; nt < 8; ++nt)
#pragma unroll
            for (int q = 0; q < 4; ++q) acc[mt][nt][q] = 0.f;

    const int barid = 2 + g1;

    // entry: chunk 0 W ready
    MBAR_WAIT(mbb + 0, 0u);
    BAR_HALF(barid);

    const float* pl = pa + NS * KC;       // next chunk to load (chunk 3)
    int ph0 = 1, ph1 = 0, ph2 = 0;        // slot0 phase consumed once
    int cs = 0;
    for (int i = 0; i < NITER; ++i) {
        float4 v[4];
        const bool more = (i + NS < NITER);
        if (more) {
#pragma unroll
            for (int j = 0; j < 4; ++j) v[j] = *(const float4*)(pl + j * rstep);
            pl += KC;
        }

        const U32 st = sb + SM_SLOT + (U32)(cs * SLOT_BYTES);
#pragma unroll
        for (int ks = 0; ks < 2; ++ks) {
            const U32 kb = (U32)(ks * 32);
            U32 a[2][4];
#pragma unroll
            for (int mt = 0; mt < 2; ++mt)
                ldsm4(a[mt][0], a[mt][1], a[mt][2], a[mt][3], st + aOff[mt] + kb);
#pragma unroll
            for (int g = 0; g < 2; ++g) {
                U32 b0[4], b1[4];
                ldsm4(b0[0], b0[1], b0[2], b0[3], st + bOff[g] + kb);
                ldsm4(b1[0], b1[1], b1[2], b1[3], st + bOff[g] + kb + 16u);
#pragma unroll
                for (int mt = 0; mt < 2; ++mt)
#pragma unroll
                    for (int j = 0; j < 4; ++j)
                        mma16(acc[mt][4 * g + j], a[mt][0], a[mt][1], a[mt][2], a[mt][3],
                              b0[j], b1[j]);
            }
        }

        if (i + 1 < NITER) {
            const int ws = (cs == NS - 1) ? 0 : cs + 1;    // slot of chunk i+1
            int ph = (ws == 0) ? ph0 : (ws == 1) ? ph1 : ph2;
            MBAR_WAIT(mbb + ws * 8, (U32)ph);
            if (ws == 0) ph0 ^= 1; else if (ws == 1) ph1 ^= 1; else ph2 ^= 1;
            BAR_HALF(barid);
            if (more) {
                stash(st, v);                              // chunk i+NS -> slot cs
                if (htid == 0) {
                    mbar_expect(mbb + cs * 8, W_BYTES);
                    bulk_g2s(st + toW, gw + (size_t)(i + NS) * PANEL_H, W_BYTES, mbb + cs * 8);
                }
            }
        }
        cs = (cs == NS - 1) ? 0 : cs + 1;
    }
    __syncthreads();

    // ---------- epilogue ----------
    float* exch = (float*)(smem + SM_SLOT);    // reuse slot area: 64 x EXP fp32
    const float* sa0 = (const float*)(smem + SM_COEF);
    const float* sa1 = sa0 + 128;
    const float* sbs = sa0 + 256;

    const int rowb = mw * 32 + (lid >> 2);
    const int colb = nw * 64 + 2 * (lid & 3);

    if (!g1) {
#pragma unroll
        for (int mt = 0; mt < 2; ++mt) {
            const int rl = rowb + mt * 16;
#pragma unroll
            for (int nt = 0; nt < 8; ++nt) {
                const int c = colb + nt * 8;
                float2 v0 = make_float2(acc[mt][nt][0], acc[mt][nt][1]);
                float2 v1 = make_float2(acc[mt][nt][2], acc[mt][nt][3]);
                *(float2*)(out + (size_t)(m0 + rl)     * ODIM + c) = v0;
                *(float2*)(out + (size_t)(m0 + rl + 8) * ODIM + c) = v1;
                *(float2*)(exch + rl * EXP + c)       = v0;
                *(float2*)(exch + (rl + 8) * EXP + c) = v1;
            }
        }
    } else {
        float* o1 = out + (size_t)BATCHN * ODIM;
#pragma unroll
        for (int mt = 0; mt < 2; ++mt) {
            const int rl = rowb + mt * 16;
#pragma unroll
            for (int nt = 0; nt < 8; ++nt) {
                const int c = colb + nt * 8;
                *(float2*)(o1 + (size_t)(m0 + rl)     * ODIM + c) =
                    make_float2(acc[mt][nt][0], acc[mt][nt][1]);
                *(float2*)(o1 + (size_t)(m0 + rl + 8) * ODIM + c) =
                    make_float2(acc[mt][nt][2], acc[mt][nt][3]);
            }
        }
    }
    __syncthreads();

    if (g1) {
        float* o2 = out + 2 * (size_t)BATCHN * ODIM;
#pragma unroll
        for (int mt = 0; mt < 2; ++mt) {
            const int rl = rowb + mt * 16;
#pragma unroll
            for (int nt = 0; nt < 8; ++nt) {
                const int c = colb + nt * 8;
                float2 p0 = *(const float2*)(exch + rl * EXP + c);
                float2 p1 = *(const float2*)(exch + (rl + 8) * EXP + c);
                const float A0x = sa0[c], A0y = sa0[c + 1];
                const float A1x = sa1[c], A1y = sa1[c + 1];
                const float Bx  = sbs[c], By  = sbs[c + 1];
                float2 r0, r1;
                r0.x = p0.x * A0x + acc[mt][nt][0] * A1x + Bx;
                r0.y = p0.y * A0y + acc[mt][nt][1] * A1y + By;
                r1.x = p1.x * A0x + acc[mt][nt][2] * A1x + Bx;
                r1.y = p1.y * A0y + acc[mt][nt][3] * A1y + By;
                *(float2*)(o2 + (size_t)(m0 + rl)     * ODIM + c) = r0;
                *(float2*)(o2 + (size_t)(m0 + rl + 8) * ODIM + c) = r1;
            }
        }
    }
}

// ---------------- launch ----------------

extern "C" void kernel_launch(void* const* d_in, const int* in_sizes, int n_in,
                              void* d_out, int out_size) {
    const float* x  = (const float*)d_in[0];
    const float* y  = (const float*)d_in[1];
    const float* fw = (const float*)d_in[2];
    const float* fb = (const float*)d_in[3];
    const float* a0 = (const float*)d_in[4];
    const float* a1 = (const float*)d_in[5];
    float* out = (float*)d_out;

    normalize_kernel<<<2 * ODIM, 256>>>(fw);

    cudaFuncSetAttribute(gemm_kernel, cudaFuncAttributeMaxDynamicSharedMemorySize, SMEM_TOTAL);
    gemm_kernel<<<BATCHN / BM, NTHR, SMEM_TOTAL>>>(x, y, fb, a0, a1, out);
}